// round 1
// baseline (speedup 1.0000x reference)
#include <cuda_runtime.h>

#define N_NODES 50000
#define DIM 128
#define NHEAD 8

// ---- scratch (static device globals; no runtime allocation) ----
__device__ float g_x[N_NODES * DIM];      // projected features [N,128]
__device__ float g_al[N_NODES * NHEAD];   // left logits  [N,8]
__device__ float g_ar[N_NODES * NHEAD];   // right logits [N,8]
__device__ float g_denom[N_NODES * NHEAD];// softmax denominators [N,8]
__device__ float g_feat[N_NODES * DIM];   // aggregated messages [N,128]

// ---------------- init: zero feat + denom ----------------
__global__ void k_init() {
    int i = blockIdx.x * blockDim.x + threadIdx.x;
    const int NF4 = N_NODES * DIM / 4;    // 1,600,000 float4
    const int ND4 = N_NODES * NHEAD / 4;  // 100,000 float4
    float4 z = make_float4(0.f, 0.f, 0.f, 0.f);
    if (i < NF4) {
        reinterpret_cast<float4*>(g_feat)[i] = z;
    } else if (i < NF4 + ND4) {
        reinterpret_cast<float4*>(g_denom)[i - NF4] = z;
    }
}

// ---------------- fused dual GEMM: x = F@Wlin, res = F@Wres ----------------
// grid = (ceil(N/32), 2); blockIdx.y selects weight/output.
// Block: 256 threads = 8 warps; warp w owns nodes [4w,4w+4); lane l owns cols
// {l, l+32, l+64, l+96}. K tiled in 2 chunks of 64 (smem = 40KB).
__global__ __launch_bounds__(256) void k_gemm(const float* __restrict__ feature,
                                              const float* __restrict__ w_lin,
                                              const float* __restrict__ w_res,
                                              float* __restrict__ d_out) {
    __shared__ float sW[64][128];
    __shared__ float sF[32][64];
    const float* __restrict__ W = (blockIdx.y == 0) ? w_lin : w_res;
    float* out = (blockIdx.y == 0) ? g_x : d_out;
    const int node0 = blockIdx.x * 32;
    const int warp = threadIdx.x >> 5;
    const int lane = threadIdx.x & 31;

    float acc[4][4] = {};
    for (int kt = 0; kt < 2; kt++) {
        __syncthreads();
        // load W rows [kt*64, kt*64+64) x 128 cols
        for (int i = threadIdx.x; i < 64 * 32; i += 256) {
            int r = i >> 5, c4 = i & 31;
            float4 v = reinterpret_cast<const float4*>(W + (kt * 64 + r) * 128)[c4];
            reinterpret_cast<float4*>(&sW[r][0])[c4] = v;
        }
        // load feature chunk: 32 nodes x 64 k
        for (int i = threadIdx.x; i < 32 * 16; i += 256) {
            int n = i >> 4, c4 = i & 15;
            int node = node0 + n;
            float4 v = make_float4(0.f, 0.f, 0.f, 0.f);
            if (node < N_NODES)
                v = reinterpret_cast<const float4*>(feature + node * 128 + kt * 64)[c4];
            reinterpret_cast<float4*>(&sF[n][0])[c4] = v;
        }
        __syncthreads();
        #pragma unroll 8
        for (int k = 0; k < 64; k++) {
            float f0 = sF[warp * 4 + 0][k];
            float f1 = sF[warp * 4 + 1][k];
            float f2 = sF[warp * 4 + 2][k];
            float f3 = sF[warp * 4 + 3][k];
            #pragma unroll
            for (int j = 0; j < 4; j++) {
                float wv = sW[k][lane + 32 * j];
                acc[0][j] += f0 * wv;
                acc[1][j] += f1 * wv;
                acc[2][j] += f2 * wv;
                acc[3][j] += f3 * wv;
            }
        }
    }
    #pragma unroll
    for (int nn = 0; nn < 4; nn++) {
        int node = node0 + warp * 4 + nn;
        if (node < N_NODES) {
            #pragma unroll
            for (int j = 0; j < 4; j++)
                out[node * 128 + lane + 32 * j] = acc[nn][j];
        }
    }
}

// ---------------- per-node attention logits ----------------
__global__ void k_alar(const float* __restrict__ att_l, const float* __restrict__ att_r) {
    int id = blockIdx.x * blockDim.x + threadIdx.x;
    if (id >= N_NODES * NHEAD) return;
    int n = id >> 3, h = id & 7;
    const float4* xr = reinterpret_cast<const float4*>(g_x + n * 128 + h * 16);
    const float4* lp = reinterpret_cast<const float4*>(att_l + h * 16);
    const float4* rp = reinterpret_cast<const float4*>(att_r + h * 16);
    float sl = 0.f, sr = 0.f;
    #pragma unroll
    for (int c = 0; c < 4; c++) {
        float4 xv = xr[c], lv = lp[c], rv = rp[c];
        sl += xv.x * lv.x + xv.y * lv.y + xv.z * lv.z + xv.w * lv.w;
        sr += xv.x * rv.x + xv.y * rv.y + xv.z * rv.z + xv.w * rv.w;
    }
    g_al[id] = sl;
    g_ar[id] = sr;
}

// ---------------- edge pass: one warp per edge ----------------
// Softmax max-subtraction dropped (cancels exactly in coef; logits bounded).
// denom[dst,h] += exp(a);  feat[dst,:] += exp(a) * x[src,:]
__global__ __launch_bounds__(256) void k_edge(const int* __restrict__ esrc,
                                              const int* __restrict__ edst,
                                              const float* __restrict__ ew,
                                              int E) {
    int e = (blockIdx.x * blockDim.x + threadIdx.x) >> 5;
    if (e >= E) return;
    int lane = threadIdx.x & 31;
    int s = __ldg(esrc + e);
    int d = __ldg(edst + e);
    float wt = __ldg(ew + e);
    int h = lane >> 2;  // 4 lanes per head, 4 cols per lane
    float a = wt * (g_al[s * 8 + h] + g_ar[d * 8 + h]);
    a = (a > 0.f) ? a : 0.2f * a;      // leaky relu
    float ee = __expf(a);
    if ((lane & 3) == 0) atomicAdd(&g_denom[d * 8 + h], ee);
    float4 xv = *reinterpret_cast<const float4*>(g_x + s * 128 + lane * 4);
    float mx = ee * xv.x, my = ee * xv.y, mz = ee * xv.z, mw = ee * xv.w;
    float* addr = g_feat + d * 128 + lane * 4;
    asm volatile("red.global.add.v4.f32 [%0], {%1, %2, %3, %4};"
                 :: "l"(addr), "f"(mx), "f"(my), "f"(mz), "f"(mw)
                 : "memory");
}

// ---------------- finalize: out = elu(feat/denom) + res ----------------
// d_out already holds the residual (written by k_gemm blockIdx.y==1).
__global__ void k_final(float* __restrict__ d_out) {
    int i = blockIdx.x * blockDim.x + threadIdx.x;  // float4 index
    if (i >= N_NODES * DIM / 4) return;
    int n = i >> 5;
    int c4 = i & 31;
    int h = c4 >> 2;
    float dnm = g_denom[n * 8 + h];
    float inv = (dnm > 0.f) ? 1.f / dnm : 0.f;
    float4 f = reinterpret_cast<const float4*>(g_feat)[i];
    float4 o = reinterpret_cast<float4*>(d_out)[i];
    float v;
    v = f.x * inv; o.x += (v > 0.f) ? v : (__expf(v) - 1.f);
    v = f.y * inv; o.y += (v > 0.f) ? v : (__expf(v) - 1.f);
    v = f.z * inv; o.z += (v > 0.f) ? v : (__expf(v) - 1.f);
    v = f.w * inv; o.w += (v > 0.f) ? v : (__expf(v) - 1.f);
    reinterpret_cast<float4*>(d_out)[i] = o;
}

extern "C" void kernel_launch(void* const* d_in, const int* in_sizes, int n_in,
                              void* d_out, int out_size) {
    const float* feature = (const float*)d_in[0];
    const int*   esrc    = (const int*)d_in[1];
    const int*   edst    = (const int*)d_in[2];
    const float* ew      = (const float*)d_in[3];
    const float* w_lin   = (const float*)d_in[4];
    const float* att_l   = (const float*)d_in[5];
    const float* att_r   = (const float*)d_in[6];
    const float* w_res   = (const float*)d_in[7];
    float* out = (float*)d_out;
    const int E = in_sizes[1];

    const int NINIT4 = N_NODES * DIM / 4 + N_NODES * NHEAD / 4;
    k_init<<<(NINIT4 + 255) / 256, 256>>>();

    dim3 gg((N_NODES + 31) / 32, 2);
    k_gemm<<<gg, 256>>>(feature, w_lin, w_res, out);

    k_alar<<<(N_NODES * NHEAD + 255) / 256, 256>>>(att_l, att_r);

    long long tot = (long long)E * 32;
    k_edge<<<(int)((tot + 255) / 256), 256>>>(esrc, edst, ew, E);

    k_final<<<(N_NODES * DIM / 4 + 255) / 256, 256>>>(out);
}

// round 3
// speedup vs baseline: 1.4467x; 1.4467x over previous
#include <cuda_runtime.h>

#define N_NODES 50000
#define N_EDGES 1600000
#define DIM 128
#define NHEAD 8

// ---- scratch (static device globals; no runtime allocation) ----
__device__ float g_x[N_NODES * DIM];        // projected features [N,128]
__device__ float g_al[N_NODES * NHEAD];     // left logits  [N,8]
__device__ float g_ar[N_NODES * NHEAD];     // right logits [N,8]
__device__ int   g_count[N_NODES];          // per-dst edge counts
__device__ int   g_rowptr[N_NODES + 1];     // CSR row pointers
__device__ int   g_cursor[N_NODES];         // scatter cursors
__device__ int2  g_edge[N_EDGES];           // dst-sorted (src, weight_bits)

// ---------------- zero counters ----------------
__global__ void k_zero() {
    int i = blockIdx.x * blockDim.x + threadIdx.x;
    if (i < N_NODES) g_count[i] = 0;
}

// ---------------- fused dual GEMM: x = F@Wlin, res = F@Wres ----------------
__global__ __launch_bounds__(256) void k_gemm(const float* __restrict__ feature,
                                              const float* __restrict__ w_lin,
                                              const float* __restrict__ w_res,
                                              float* __restrict__ d_out) {
    __shared__ float sW[64][128];
    __shared__ float sF[32][64];
    const float* __restrict__ W = (blockIdx.y == 0) ? w_lin : w_res;
    float* out = (blockIdx.y == 0) ? g_x : d_out;
    const int node0 = blockIdx.x * 32;
    const int warp = threadIdx.x >> 5;
    const int lane = threadIdx.x & 31;

    float acc[4][4] = {};
    for (int kt = 0; kt < 2; kt++) {
        __syncthreads();
        for (int i = threadIdx.x; i < 64 * 32; i += 256) {
            int r = i >> 5, c4 = i & 31;
            float4 v = reinterpret_cast<const float4*>(W + (kt * 64 + r) * 128)[c4];
            reinterpret_cast<float4*>(&sW[r][0])[c4] = v;
        }
        for (int i = threadIdx.x; i < 32 * 16; i += 256) {
            int n = i >> 4, c4 = i & 15;
            int node = node0 + n;
            float4 v = make_float4(0.f, 0.f, 0.f, 0.f);
            if (node < N_NODES)
                v = reinterpret_cast<const float4*>(feature + node * 128 + kt * 64)[c4];
            reinterpret_cast<float4*>(&sF[n][0])[c4] = v;
        }
        __syncthreads();
        #pragma unroll 8
        for (int k = 0; k < 64; k++) {
            float f0 = sF[warp * 4 + 0][k];
            float f1 = sF[warp * 4 + 1][k];
            float f2 = sF[warp * 4 + 2][k];
            float f3 = sF[warp * 4 + 3][k];
            #pragma unroll
            for (int j = 0; j < 4; j++) {
                float wv = sW[k][lane + 32 * j];
                acc[0][j] += f0 * wv;
                acc[1][j] += f1 * wv;
                acc[2][j] += f2 * wv;
                acc[3][j] += f3 * wv;
            }
        }
    }
    #pragma unroll
    for (int nn = 0; nn < 4; nn++) {
        int node = node0 + warp * 4 + nn;
        if (node < N_NODES) {
            #pragma unroll
            for (int j = 0; j < 4; j++)
                out[node * 128 + lane + 32 * j] = acc[nn][j];
        }
    }
}

// ---------------- per-node attention logits ----------------
__global__ void k_alar(const float* __restrict__ att_l, const float* __restrict__ att_r) {
    int id = blockIdx.x * blockDim.x + threadIdx.x;
    if (id >= N_NODES * NHEAD) return;
    int n = id >> 3, h = id & 7;
    const float4* xr = reinterpret_cast<const float4*>(g_x + n * 128 + h * 16);
    const float4* lp = reinterpret_cast<const float4*>(att_l + h * 16);
    const float4* rp = reinterpret_cast<const float4*>(att_r + h * 16);
    float sl = 0.f, sr = 0.f;
    #pragma unroll
    for (int c = 0; c < 4; c++) {
        float4 xv = xr[c], lv = lp[c], rv = rp[c];
        sl += xv.x * lv.x + xv.y * lv.y + xv.z * lv.z + xv.w * lv.w;
        sr += xv.x * rv.x + xv.y * rv.y + xv.z * rv.z + xv.w * rv.w;
    }
    g_al[id] = sl;
    g_ar[id] = sr;
}

// ---------------- histogram of dst ----------------
__global__ void k_hist(const int* __restrict__ edst, int E) {
    int e = blockIdx.x * blockDim.x + threadIdx.x;
    if (e < E) atomicAdd(&g_count[edst[e]], 1);
}

// ---------------- single-block exclusive scan over 50K counts ----------------
__global__ __launch_bounds__(1024) void k_scan() {
    __shared__ int warp_sums[32];
    __shared__ int s_carry;
    int tid = threadIdx.x, lane = tid & 31, wid = tid >> 5;
    if (tid == 0) s_carry = 0;
    __syncthreads();
    for (int base = 0; base < N_NODES; base += 1024) {
        int i = base + tid;
        int v = (i < N_NODES) ? g_count[i] : 0;
        int incl = v;
        #pragma unroll
        for (int o = 1; o < 32; o <<= 1) {
            int t = __shfl_up_sync(0xFFFFFFFFu, incl, o);
            if (lane >= o) incl += t;
        }
        if (lane == 31) warp_sums[wid] = incl;
        __syncthreads();
        if (wid == 0) {
            int ws = warp_sums[lane];
            int wincl = ws;
            #pragma unroll
            for (int o = 1; o < 32; o <<= 1) {
                int t = __shfl_up_sync(0xFFFFFFFFu, wincl, o);
                if (lane >= o) wincl += t;
            }
            warp_sums[lane] = wincl - ws;   // exclusive warp prefix
        }
        __syncthreads();
        int excl = incl - v + warp_sums[wid] + s_carry;
        if (i < N_NODES) { g_rowptr[i] = excl; g_cursor[i] = excl; }
        __syncthreads();                     // all reads of s_carry/warp_sums done
        if (tid == 1023) s_carry += warp_sums[31] + incl;  // chunk total
        __syncthreads();
    }
    if (threadIdx.x == 0) g_rowptr[N_NODES] = s_carry;
}

// ---------------- scatter edges into dst-sorted order ----------------
__global__ void k_scatter(const int* __restrict__ esrc, const int* __restrict__ edst,
                          const float* __restrict__ ew, int E) {
    int e = blockIdx.x * blockDim.x + threadIdx.x;
    if (e >= E) return;
    int d = edst[e];
    int pos = atomicAdd(&g_cursor[d], 1);
    g_edge[pos] = make_int2(esrc[e], __float_as_int(ew[e]));
}

// ---------------- aggregate: one warp per dst node, fused finalize ----------------
// denom and message accumulated in registers; out = elu(msg/denom) + res.
// 4-deep pipelining: batch loads for 4 edges before consuming (hide L2 latency).
__global__ __launch_bounds__(256) void k_agg(float* __restrict__ d_out) {
    int node = (blockIdx.x * blockDim.x + threadIdx.x) >> 5;
    if (node >= N_NODES) return;
    int lane = threadIdx.x & 31;
    int h = lane >> 2;                      // 4 lanes per head, 4 cols per lane
    int beg = __ldg(&g_rowptr[node]);
    int end = __ldg(&g_rowptr[node + 1]);
    float arv = g_ar[node * 8 + h];

    float a0 = 0.f, a1 = 0.f, a2 = 0.f, a3 = 0.f, dsum = 0.f;
    int e = beg;
    for (; e + 4 <= end; e += 4) {
        int2 ed[4];
        #pragma unroll
        for (int j = 0; j < 4; j++) ed[j] = __ldg(&g_edge[e + j]);
        float al[4];
        float4 xv[4];
        #pragma unroll
        for (int j = 0; j < 4; j++) {
            al[j] = __ldg(&g_al[ed[j].x * 8 + h]);
            xv[j] = __ldg(reinterpret_cast<const float4*>(g_x + ed[j].x * 128 + lane * 4));
        }
        #pragma unroll
        for (int j = 0; j < 4; j++) {
            float aa = __int_as_float(ed[j].y) * (al[j] + arv);
            aa = (aa > 0.f) ? aa : 0.2f * aa;
            float ee = __expf(aa);
            dsum += ee;
            a0 += ee * xv[j].x;
            a1 += ee * xv[j].y;
            a2 += ee * xv[j].z;
            a3 += ee * xv[j].w;
        }
    }
    for (; e < end; e++) {
        int2 e0 = __ldg(&g_edge[e]);
        float al0 = __ldg(&g_al[e0.x * 8 + h]);
        float4 x0 = __ldg(reinterpret_cast<const float4*>(g_x + e0.x * 128 + lane * 4));
        float aa0 = __int_as_float(e0.y) * (al0 + arv);
        aa0 = (aa0 > 0.f) ? aa0 : 0.2f * aa0;
        float ee0 = __expf(aa0);
        dsum += ee0;
        a0 += ee0 * x0.x; a1 += ee0 * x0.y; a2 += ee0 * x0.z; a3 += ee0 * x0.w;
    }

    float inv = (dsum > 0.f) ? 1.f / dsum : 0.f;
    float4 o = reinterpret_cast<float4*>(d_out)[node * 32 + lane];
    float v;
    v = a0 * inv; o.x += (v > 0.f) ? v : (__expf(v) - 1.f);
    v = a1 * inv; o.y += (v > 0.f) ? v : (__expf(v) - 1.f);
    v = a2 * inv; o.z += (v > 0.f) ? v : (__expf(v) - 1.f);
    v = a3 * inv; o.w += (v > 0.f) ? v : (__expf(v) - 1.f);
    reinterpret_cast<float4*>(d_out)[node * 32 + lane] = o;
}

extern "C" void kernel_launch(void* const* d_in, const int* in_sizes, int n_in,
                              void* d_out, int out_size) {
    const float* feature = (const float*)d_in[0];
    const int*   esrc    = (const int*)d_in[1];
    const int*   edst    = (const int*)d_in[2];
    const float* ew      = (const float*)d_in[3];
    const float* w_lin   = (const float*)d_in[4];
    const float* att_l   = (const float*)d_in[5];
    const float* att_r   = (const float*)d_in[6];
    const float* w_res   = (const float*)d_in[7];
    float* out = (float*)d_out;
    const int E = in_sizes[1];

    k_zero<<<(N_NODES + 255) / 256, 256>>>();

    dim3 gg((N_NODES + 31) / 32, 2);
    k_gemm<<<gg, 256>>>(feature, w_lin, w_res, out);

    k_alar<<<(N_NODES * NHEAD + 255) / 256, 256>>>(att_l, att_r);

    k_hist<<<(E + 255) / 256, 256>>>(edst, E);
    k_scan<<<1, 1024>>>();
    k_scatter<<<(E + 255) / 256, 256>>>(esrc, edst, ew, E);

    k_agg<<<(N_NODES * 32 + 255) / 256, 256>>>(out);
}